// round 2
// baseline (speedup 1.0000x reference)
#include <cuda_runtime.h>

#define Hdim 128
#define SROW 132   // smem row stride in floats (16B-aligned rows: 132*4=528)

// ---------------------------------------------------------------------------
// Packed-pair weight scratch: for each layer W (K x 128), store
// Wp[kp*128 + c] = (W[2kp][c], W[2kp+1][c])  (hi = 0 past K).
// Regions (float2 offsets):
//   nem0:0(128 pairs) nem1:16384 nem2:24576 | mg0:32768 mg1:49152 mg2:57344
//   mr0:65536(65 pairs) mr1:73856 mr2:82048 | total 90240
// ---------------------------------------------------------------------------
__device__ float2 g_Wp[90240];
#define OFF_NEM0 0
#define OFF_NEM1 16384
#define OFF_NEM2 24576
#define OFF_MG0  32768
#define OFF_MG1  49152
#define OFF_MG2  57344
#define OFF_MR0  65536
#define OFF_MR1  73856
#define OFF_MR2  82048
#define WP_TOTAL 90240

struct Srcs { const float* p[9]; };

__global__ void repack_kernel(Srcs srcs) {
    const int offs[10] = {0,16384,24576,32768,49152,57344,65536,73856,82048,90240};
    const int Ks[9]    = {256,128,128,256,128,128,129,128,128};
    int idx = blockIdx.x * blockDim.x + threadIdx.x;
    if (idx >= WP_TOTAL) return;
    int r = 0;
#pragma unroll
    for (int j = 1; j < 9; j++) if (idx >= offs[j]) r = j;
    int local = idx - offs[r];
    int kp = local >> 7, c = local & 127;
    const float* W = srcs.p[r];
    int K = Ks[r];
    float lo = W[(2 * kp) * Hdim + c];
    float hi = (2 * kp + 1 < K) ? W[(2 * kp + 1) * Hdim + c] : 0.f;
    g_Wp[idx] = make_float2(lo, hi);
}

// ---------------------------------------------------------------------------
// Packed fp32 helpers (sm_103a f32x2 pipe: 2 FMA per instruction)
// ---------------------------------------------------------------------------
typedef unsigned long long u64;

__device__ __forceinline__ u64 ffma2(u64 a, u64 b, u64 c) {
    u64 d;
    asm("fma.rn.f32x2 %0, %1, %2, %3;" : "=l"(d) : "l"(a), "l"(b), "l"(c));
    return d;
}
__device__ __forceinline__ u64 pk2(float lo, float hi) {
    return ((u64)__float_as_uint(hi) << 32) | (u64)__float_as_uint(lo);
}
__device__ __forceinline__ float redp(u64 d) {
    return __int_as_float((int)(unsigned)(d & 0xffffffffull)) +
           __int_as_float((int)(unsigned)(d >> 32));
}
__device__ __forceinline__ u64 d2u_lo(double2 v) { return (u64)__double_as_longlong(v.x); }
__device__ __forceinline__ u64 d2u_hi(double2 v) { return (u64)__double_as_longlong(v.y); }

// ---------------------------------------------------------------------------
// Accumulate 128 input features (64 k-pairs) into acc[RPW][4].
// Weight pairs via LDG.128 (L1-resident); activation pairs via broadcast LDS.
// ---------------------------------------------------------------------------
template<int RPW, bool INIT>
__device__ __forceinline__ void accum64(
    const float2* __restrict__ Wp,
    const float* __restrict__ ins, int r0, int c0,
    u64 (&acc)[RPW][4], const float* __restrict__ Bv)
{
    if (INIT) {
        float4 b = *(const float4*)(Bv + c0);
#pragma unroll
        for (int i = 0; i < RPW; i++) {
            acc[i][0] = pk2(b.x, 0.f); acc[i][1] = pk2(b.y, 0.f);
            acc[i][2] = pk2(b.z, 0.f); acc[i][3] = pk2(b.w, 0.f);
        }
    }
    const float2* wbase = Wp + c0;
#pragma unroll 2
    for (int kk = 0; kk < 32; kk++) {
        const double2* wa = (const double2*)(wbase + (2 * kk) * Hdim);
        const double2* wb = (const double2*)(wbase + (2 * kk + 1) * Hdim);
        double2 wA = __ldg(wa), wA1 = __ldg(wa + 1);
        double2 wB = __ldg(wb), wB1 = __ldg(wb + 1);
        u64 wa0 = d2u_lo(wA),  wa1 = d2u_hi(wA);
        u64 wa2 = d2u_lo(wA1), wa3 = d2u_hi(wA1);
        u64 wb0 = d2u_lo(wB),  wb1 = d2u_hi(wB);
        u64 wb2 = d2u_lo(wB1), wb3 = d2u_hi(wB1);
#pragma unroll
        for (int i = 0; i < RPW; i++) {
            double2 av = *(const double2*)(ins + (r0 + i) * SROW + 4 * kk);
            u64 ax = d2u_lo(av), ay = d2u_hi(av);
            acc[i][0] = ffma2(ax, wa0, acc[i][0]);
            acc[i][1] = ffma2(ax, wa1, acc[i][1]);
            acc[i][2] = ffma2(ax, wa2, acc[i][2]);
            acc[i][3] = ffma2(ax, wa3, acc[i][3]);
            acc[i][0] = ffma2(ay, wb0, acc[i][0]);
            acc[i][1] = ffma2(ay, wb1, acc[i][1]);
            acc[i][2] = ffma2(ay, wb2, acc[i][2]);
            acc[i][3] = ffma2(ay, wb3, acc[i][3]);
        }
    }
}

template<int RPW, bool RELU>
__device__ __forceinline__ void emit(u64 (&acc)[RPW][4], float* outs, int r0, int c0) {
#pragma unroll
    for (int i = 0; i < RPW; i++) {
        float4 v;
        v.x = redp(acc[i][0]); v.y = redp(acc[i][1]);
        v.z = redp(acc[i][2]); v.w = redp(acc[i][3]);
        if (RELU) {
            v.x = fmaxf(v.x, 0.f); v.y = fmaxf(v.y, 0.f);
            v.z = fmaxf(v.z, 0.f); v.w = fmaxf(v.w, 0.f);
        }
        *(float4*)(outs + (r0 + i) * SROW + c0) = v;
    }
}

// ---------------------------------------------------------------------------
// Fused gather -> 3-layer MLP -> scatter.
// mode 0 (nem):  in = [x_in[esrc[row]], efeat[row]], out -> xw[edst[row]]
// mode 1 (mg):   in = [xw[esrc[s+row]], xw[esrc[s+half+row]]],
//                out -> xw[edst[s+half+row]]
// mode 2 (mr):   in = [xw[edst[s+row]], state], out: xw[src] = mlp + xw[src]
// mode 3 (mr leaf): bottom read from x_in instead of xw
// ---------------------------------------------------------------------------
template<int RPW>
__global__ void __launch_bounds__(256)
mlp2_kernel(const float* __restrict__ x_in, float* __restrict__ xw,
            const int* __restrict__ esrc, const int* __restrict__ edst,
            const float* __restrict__ estates, const float* __restrict__ efeat,
            const float2* __restrict__ L0, const float* __restrict__ B0,
            const float2* __restrict__ L1, const float* __restrict__ B1,
            const float2* __restrict__ L2, const float* __restrict__ B2,
            int s, int M, int half, int mode)
{
    extern __shared__ float sm[];
    const int TILE = 8 * RPW;
    float* Xs = sm;                      // [TILE][SROW]
    float* Hs = sm + TILE * SROW;        // [TILE][SROW]

    int lane = threadIdx.x & 31;
    int warp = threadIdx.x >> 5;
    int r0 = warp * RPW;
    int grow0 = blockIdx.x * TILE + r0;
    if (grow0 >= M) return;
    int c0 = lane * 4;

    u64 acc[RPW][4];
    float st[RPW];

    // ---- gather first 128 inputs ----
#pragma unroll
    for (int i = 0; i < RPW; i++) {
        int grow = grow0 + i;
        if (grow >= M) break;
        float* xr = Xs + (r0 + i) * SROW;
        const float* srcp;
        if (mode == 0)      srcp = x_in + (size_t)esrc[grow] * Hdim;
        else if (mode == 1) srcp = xw + (size_t)esrc[s + grow] * Hdim;
        else { srcp = xw + (size_t)edst[s + grow] * Hdim; st[i] = estates[s + grow]; }
        ((float4*)xr)[lane] = ((const float4*)srcp)[lane];
    }
    __syncwarp();
    accum64<RPW, true>(L0, Xs, r0, c0, acc, B0);
    __syncwarp();

    if (mode <= 1) {
        // ---- gather second 128 inputs, accumulate ----
#pragma unroll
        for (int i = 0; i < RPW; i++) {
            int grow = grow0 + i;
            if (grow >= M) break;
            float* xr = Xs + (r0 + i) * SROW;
            const float* srcp = (mode == 0)
                ? efeat + (size_t)grow * Hdim
                : xw + (size_t)esrc[s + half + grow] * Hdim;
            ((float4*)xr)[lane] = ((const float4*)srcp)[lane];
        }
        __syncwarp();
        accum64<RPW, false>(L0 + 64 * Hdim, Xs, r0, c0, acc, B0);
    } else {
        // ---- state term: pair index 64 of mr layer 0 (hi weight is 0) ----
        const double2* ws = (const double2*)(L0 + 64 * Hdim + c0);
        double2 wS = __ldg(ws), wS1 = __ldg(ws + 1);
        u64 w0 = d2u_lo(wS), w1 = d2u_hi(wS), w2 = d2u_lo(wS1), w3 = d2u_hi(wS1);
#pragma unroll
        for (int i = 0; i < RPW; i++) {
            u64 aS = pk2(st[i], st[i]);
            acc[i][0] = ffma2(aS, w0, acc[i][0]);
            acc[i][1] = ffma2(aS, w1, acc[i][1]);
            acc[i][2] = ffma2(aS, w2, acc[i][2]);
            acc[i][3] = ffma2(aS, w3, acc[i][3]);
        }
    }

    emit<RPW, true>(acc, Hs, r0, c0);
    __syncwarp();
    accum64<RPW, true>(L1, Hs, r0, c0, acc, B1);
    emit<RPW, true>(acc, Xs, r0, c0);
    __syncwarp();
    accum64<RPW, true>(L2, Xs, r0, c0, acc, B2);

    // ---- scatter from registers ----
#pragma unroll
    for (int i = 0; i < RPW; i++) {
        int grow = grow0 + i;
        if (grow >= M) break;
        float4 v;
        v.x = redp(acc[i][0]); v.y = redp(acc[i][1]);
        v.z = redp(acc[i][2]); v.w = redp(acc[i][3]);
        int node;
        if (mode == 0)      node = edst[grow];
        else if (mode == 1) node = edst[s + half + grow];
        else                node = esrc[s + grow];
        if (mode >= 2) {
            const float* bot = ((mode == 3) ? x_in : xw) + (size_t)node * Hdim + c0;
            float4 bv = *(const float4*)bot;
            v.x += bv.x; v.y += bv.y; v.z += bv.z; v.w += bv.w;
        }
        *(float4*)(xw + (size_t)node * Hdim + c0) = v;
    }
}

// ---------------------------------------------------------------------------
// Host launcher
// ---------------------------------------------------------------------------
static void launch_phase(const float* x, float* xw,
                         const int* esrc, const int* edst,
                         const float* estates, const float* efeat,
                         const float2* L0, const float* B0,
                         const float2* L1, const float* B1,
                         const float2* L2, const float* B2,
                         long s, int M, int half, int mode)
{
    if (M <= 0) return;
    if (M >= 8192) {
        int grid = (M + 63) / 64;
        mlp2_kernel<8><<<grid, 256, 64 * 2 * SROW * 4>>>(
            x, xw, esrc, edst, estates, efeat, L0, B0, L1, B1, L2, B2,
            (int)s, M, half, mode);
    } else if (M >= 256) {
        int grid = (M + 15) / 16;
        mlp2_kernel<2><<<grid, 256, 16 * 2 * SROW * 4>>>(
            x, xw, esrc, edst, estates, efeat, L0, B0, L1, B1, L2, B2,
            (int)s, M, half, mode);
    } else {
        int grid = (M + 7) / 8;
        mlp2_kernel<1><<<grid, 256, 8 * 2 * SROW * 4>>>(
            x, xw, esrc, edst, estates, efeat, L0, B0, L1, B1, L2, B2,
            (int)s, M, half, mode);
    }
}

extern "C" void kernel_launch(void* const* d_in, const int* in_sizes, int n_in,
                              void* d_out, int out_size)
{
    (void)out_size;
    const float* x       = (const float*)d_in[0];
    const int*   esrc    = (const int*)  d_in[1];
    const int*   edst    = (const int*)  d_in[2];
    const float* estates = (const float*)d_in[3];
    const float* efeat   = (const float*)d_in[4];

    // 18 non-scalar weight tensors after index 4 (skip the size-1 gcmn_depth)
    const float* Wt[18];
    int wi = 0;
    for (int i = 5; i < n_in && wi < 18; i++) {
        if (in_sizes[i] == 1) continue;
        Wt[wi++] = (const float*)d_in[i];
    }
    const float *nb0 = Wt[1],  *nb1 = Wt[3],  *nb2 = Wt[5];
    const float *gb0 = Wt[7],  *gb1 = Wt[9],  *gb2 = Wt[11];
    const float *rb0 = Wt[13], *rb1 = Wt[15], *rb2 = Wt[17];

    int  nL      = in_sizes[4] / Hdim;       // B * N_LEAF
    long n_edges = (long)in_sizes[1];

    // Derive depth D
    int Dn = 1; long off = (long)nL;
    while (off < n_edges && Dn < 40) { off += (long)(nL >> (Dn - 1)); Dn++; }
    long boff[48]; boff[0] = 0;
    { long o = nL; for (int d = 1; d < Dn; d++) { boff[d] = o; o += (long)(nL >> (d - 1)); } }

    float* xw = (float*)d_out;

    // Repack all 9 weight matrices into k-pair-interleaved float2 layout
    float2* wp = nullptr;
    cudaGetSymbolAddress((void**)&wp, g_Wp);
    Srcs srcs;
    srcs.p[0] = Wt[0];  srcs.p[1] = Wt[2];  srcs.p[2] = Wt[4];   // nem
    srcs.p[3] = Wt[6];  srcs.p[4] = Wt[8];  srcs.p[5] = Wt[10];  // mg
    srcs.p[6] = Wt[12]; srcs.p[7] = Wt[14]; srcs.p[8] = Wt[16];  // mr
    repack_kernel<<<(WP_TOTAL + 255) / 256, 256>>>(srcs);

    cudaFuncSetAttribute(mlp2_kernel<8>, cudaFuncAttributeMaxDynamicSharedMemorySize,
                         64 * 2 * SROW * 4);

    // Phase 1: nem over all leaf edges
    launch_phase(x, xw, esrc, edst, estates, efeat,
                 wp + OFF_NEM0, nb0, wp + OFF_NEM1, nb1, wp + OFF_NEM2, nb2,
                 0, nL, 0, 0);

    // Phase 2: up-sweep (mg)
    for (int d = 1; d < Dn; d++) {
        int m = nL >> (d - 1);
        launch_phase(x, xw, esrc, edst, estates, efeat,
                     wp + OFF_MG0, gb0, wp + OFF_MG1, gb1, wp + OFF_MG2, gb2,
                     boff[d], m / 2, m / 2, 1);
    }

    // Phase 3: down-sweep (mr)
    for (int depth = Dn; depth >= 1; depth--) {
        long s; int m;
        if (depth == 1) { s = 0; m = nL; }
        else            { s = boff[depth - 1]; m = nL >> (depth - 2); }
        launch_phase(x, xw, esrc, edst, estates, efeat,
                     wp + OFF_MR0, rb0, wp + OFF_MR1, rb1, wp + OFF_MR2, rb2,
                     s, m, 0, depth == 1 ? 3 : 2);
    }
}